// round 17
// baseline (speedup 1.0000x reference)
#include <cuda_runtime.h>
#include <cuda_bf16.h>
#include <cuda_fp16.h>
#include <cuda_fp8.h>
#include <cstdint>
#include <cstddef>

#define MDIM 8192
#define KDIM 4096
#define NDIM 4096
#define BM 128
#define BN 128
#define BK 256
#define STAGES 2
#define KITERS (KDIM / BK)          // 16
#define NKB (KDIM / 128)            // 32 scale k-blocks
#define THREADS 512

// fp8 tile row: 256 B data + 16 B pad = 272 B stride.
// 8 consecutive rows -> offsets mod 128 = {0,16,32,...,112}: conflict-free ldmatrix.
#define ROW_BYTES 272
#define TILE_BYTES (128 * ROW_BYTES)          // 34816
#define STAGE_BYTES (2 * TILE_BYTES)          // A + B = 69632
#define SMEM_TOTAL (STAGES * STAGE_BYTES)     // 139264

// fused quant grid split
#define XBLOCKS (MDIM * 4)
#define WBLOCKS ((NDIM * KDIM) / 1024)

// ---- scratch (static device arrays; no allocation) ----
__device__ uint8_t g_A[(size_t)MDIM * KDIM];   // raw e4m3 bytes of quantized x
__device__ uint8_t g_W[(size_t)NDIM * KDIM];   // raw e4m3 bytes of w
__device__ float   g_SA[(size_t)MDIM * NKB];   // activation scales [M][32]

// ------------------------------ PTX helpers ------------------------------
__device__ __forceinline__ uint32_t smem_u32(const void* p) {
    uint32_t a;
    asm("{ .reg .u64 t; cvta.to.shared.u64 t, %1; cvt.u32.u64 %0, t; }" : "=r"(a) : "l"(p));
    return a;
}
__device__ __forceinline__ void cp16(uint32_t dst, const void* src) {
    asm volatile("cp.async.cg.shared.global [%0], [%1], 16;" :: "r"(dst), "l"(src) : "memory");
}
__device__ __forceinline__ void cp_commit() {
    asm volatile("cp.async.commit_group;" ::: "memory");
}
template <int N>
__device__ __forceinline__ void cp_wait() {
    asm volatile("cp.async.wait_group %0;" :: "n"(N) : "memory");
}
__device__ __forceinline__ void ldsm_x4(uint32_t* r, uint32_t addr) {
    asm volatile("ldmatrix.sync.aligned.m8n8.x4.shared.b16 {%0,%1,%2,%3}, [%4];"
                 : "=r"(r[0]), "=r"(r[1]), "=r"(r[2]), "=r"(r[3]) : "r"(addr));
}
// fp8 e4m3 MMA k32, accumulate into c
__device__ __forceinline__ void mma_fp8(float* c, const uint32_t* a, uint32_t b0, uint32_t b1) {
    asm volatile(
        "mma.sync.aligned.m16n8k32.row.col.f32.e4m3.e4m3.f32 "
        "{%0,%1,%2,%3}, {%4,%5,%6,%7}, {%8,%9}, {%0,%1,%2,%3};"
        : "+f"(c[0]), "+f"(c[1]), "+f"(c[2]), "+f"(c[3])
        : "r"(a[0]), "r"(a[1]), "r"(a[2]), "r"(a[3]), "r"(b0), "r"(b1));
}
// fp8 e4m3 MMA k32, zero accumulator input: c = a*b
__device__ __forceinline__ void mma_fp8_zc(float* c, const uint32_t* a, uint32_t b0, uint32_t b1,
                                           float z) {
    asm volatile(
        "mma.sync.aligned.m16n8k32.row.col.f32.e4m3.e4m3.f32 "
        "{%0,%1,%2,%3}, {%4,%5,%6,%7}, {%8,%9}, {%10,%10,%10,%10};"
        : "=f"(c[0]), "=f"(c[1]), "=f"(c[2]), "=f"(c[3])
        : "r"(a[0]), "r"(a[1]), "r"(a[2]), "r"(a[3]), "r"(b0), "r"(b1), "f"(z));
}
__device__ __forceinline__ uint16_t cvt_e4m3x2(float hi, float lo) {
    uint16_t r;
    asm("cvt.rn.satfinite.e4m3x2.f32 %0, %1, %2;" : "=h"(r) : "f"(hi), "f"(lo));
    return r;
}
__device__ __forceinline__ uint32_t quant4(float v0, float v1, float v2, float v3) {
    return (uint32_t)cvt_e4m3x2(v1, v0) | ((uint32_t)cvt_e4m3x2(v3, v2) << 16);
}

// ------------------------------ fused quantize kernel ------------------------------
__global__ void __launch_bounds__(256) quant_fused_kernel(const float* __restrict__ x,
                                                          const float* __restrict__ w) {
    if (blockIdx.x < XBLOCKS) {
        const int gw   = (blockIdx.x * 256 + threadIdx.x) >> 5;
        const int lane = threadIdx.x & 31;
        const int m  = gw >> 5;
        const int kb = gw & 31;
        const size_t base = (size_t)m * KDIM + kb * 128 + lane * 4;
        const float4 v = *reinterpret_cast<const float4*>(x + base);
        float amax = fmaxf(fmaxf(fabsf(v.x), fabsf(v.y)), fmaxf(fabsf(v.z), fabsf(v.w)));
#pragma unroll
        for (int o = 16; o > 0; o >>= 1)
            amax = fmaxf(amax, __shfl_xor_sync(0xFFFFFFFFu, amax, o));
        const float s = fmaxf(amax, 1e-12f) / 448.0f;
        *reinterpret_cast<uint32_t*>(g_A + base) = quant4(v.x / s, v.y / s, v.z / s, v.w / s);
        if (lane == 0) g_SA[(size_t)m * NKB + kb] = s;
    } else {
        const size_t e = ((size_t)(blockIdx.x - XBLOCKS) * 256 + threadIdx.x) * 4;
        const float4 v = *reinterpret_cast<const float4*>(w + e);
        *reinterpret_cast<uint32_t*>(g_W + e) = quant4(v.x, v.y, v.z, v.w);
    }
}

// ------------------------------ GEMM kernel ------------------------------
// 128x128x256 CTA tile, 16 warps (4m x 4n), warp tile 32x32, fp8 mma m16n8k32.
// Two scale blocks per barrier region; promote(kb0) overlaps mma(kb1),
// promote(kb1) overlaps refill + next-stage wait.
__global__ void __launch_bounds__(THREADS, 1) gemm_kernel(const float* __restrict__ wsi,
                                                          const float* __restrict__ bias,
                                                          float* __restrict__ out) {
    extern __shared__ __align__(128) char smem[];
    const uint32_t sb = smem_u32(smem);
    const int tid  = threadIdx.x;
    const int lane = tid & 31;
    const int wid  = tid >> 5;
    const int wm   = wid & 3;       // 4 warps along M
    const int wn   = wid >> 2;      // 4 warps along N
    const int m0 = blockIdx.y * BM;
    const int n0 = blockIdx.x * BN;
    const float* wsi_cta = wsi + blockIdx.x * NKB;

    float master[2][4][4];
    float temp[2][4][4];
#pragma unroll
    for (int i = 0; i < 2; ++i)
#pragma unroll
        for (int j = 0; j < 4; ++j)
#pragma unroll
            for (int q = 0; q < 4; ++q) master[i][j][q] = 0.0f;

    // producer: each thread owns one contiguous 128B half-row per tile-set:
    // tid -> tile = tid>>8 (0=A,1=B), row = (tid&255)>>1, half = tid&1; 8 cp16 each.
    const int p_tile = tid >> 8;
    const int p_row  = (tid & 255) >> 1;
    const int p_half = tid & 1;
    const uint8_t* p_src = (p_tile == 0 ? g_A + (size_t)(m0 + p_row) * KDIM
                                        : g_W + (size_t)(n0 + p_row) * KDIM) + p_half * 128;
    const uint32_t p_doff = (uint32_t)(p_tile * TILE_BYTES + p_row * ROW_BYTES + p_half * 128);

    auto load_stage = [&](int s) {
        const uint32_t dst = sb + s * STAGE_BYTES + p_doff;
#pragma unroll
        for (int i = 0; i < 8; ++i) cp16(dst + i * 16, p_src + i * 16);
        p_src += BK;
    };

    load_stage(0); cp_commit();
    load_stage(1); cp_commit();

    const int arow0 = m0 + wm * 32 + (lane >> 2);
    const float zf = 0.0f;

    for (int k = 0; k < KITERS; ++k) {
        cp_wait<1>();
        __syncthreads();

        const int kb0 = 2 * k, kb1 = 2 * k + 1;
        const float sw0 = __ldg(wsi_cta + kb0);
        const float sw1 = __ldg(wsi_cta + kb1);
        float sa0[2][2], sa1[2][2];
#pragma unroll
        for (int mi = 0; mi < 2; ++mi)
#pragma unroll
            for (int h = 0; h < 2; ++h) {
                const float* sp = g_SA + (size_t)(arow0 + mi * 16 + h * 8) * NKB;
                sa0[mi][h] = __ldg(sp + kb0);
                sa1[mi][h] = __ldg(sp + kb1);
            }

        const uint32_t aBase = sb + (k & 1) * STAGE_BYTES;
        const uint32_t bBase = aBase + TILE_BYTES;

        auto mma_block = [&](int kkBase) {
#pragma unroll
            for (int kk = 0; kk < 4; ++kk) {
                const uint32_t coff = (uint32_t)((kkBase + kk) * 32 + ((lane >> 4) << 4));
                uint32_t a[2][4];
#pragma unroll
                for (int mi = 0; mi < 2; ++mi) {
                    const int row = wm * 32 + mi * 16 + (lane & 15);
                    ldsm_x4(a[mi], aBase + (uint32_t)(row * ROW_BYTES) + coff);
                }
                uint32_t b[2][4];
#pragma unroll
                for (int nj = 0; nj < 2; ++nj) {
                    const int row = wn * 32 + nj * 16 + (((lane >> 3) & 1) << 3) + (lane & 7);
                    ldsm_x4(b[nj], bBase + (uint32_t)(row * ROW_BYTES) + coff);
                }
                if (kk == 0) {
#pragma unroll
                    for (int mi = 0; mi < 2; ++mi)
#pragma unroll
                        for (int ni = 0; ni < 4; ++ni)
                            mma_fp8_zc(temp[mi][ni], a[mi], b[ni >> 1][ni & 1],
                                       b[ni >> 1][2 + (ni & 1)], zf);
                } else {
#pragma unroll
                    for (int mi = 0; mi < 2; ++mi)
#pragma unroll
                        for (int ni = 0; ni < 4; ++ni)
                            mma_fp8(temp[mi][ni], a[mi], b[ni >> 1][ni & 1],
                                    b[ni >> 1][2 + (ni & 1)]);
                }
            }
        };
        auto promote = [&](const float sw, const float (*sa)[2]) {
#pragma unroll
            for (int mi = 0; mi < 2; ++mi) {
                const float c0 = sw * sa[mi][0];
                const float c1 = sw * sa[mi][1];
#pragma unroll
                for (int ni = 0; ni < 4; ++ni) {
                    master[mi][ni][0] = fmaf(c0, temp[mi][ni][0], master[mi][ni][0]);
                    master[mi][ni][1] = fmaf(c0, temp[mi][ni][1], master[mi][ni][1]);
                    master[mi][ni][2] = fmaf(c1, temp[mi][ni][2], master[mi][ni][2]);
                    master[mi][ni][3] = fmaf(c1, temp[mi][ni][3], master[mi][ni][3]);
                }
            }
        };

        mma_block(0);           // kb0 -> temp
        promote(sw0, sa0);      // overlaps with kb1 issue below (no barrier between)
        mma_block(4);           // kb1 -> temp (zc rewrites after promote reads)

        __syncthreads();        // all warps done reading this stage
        if (k + 2 < KITERS) load_stage(k & 1);
        cp_commit();
        promote(sw1, sa1);      // overlaps refill + next cp_wait
    }

    // -------- epilogue: bf16 arithmetic (match reference), write FLOAT32 --------
#pragma unroll
    for (int mi = 0; mi < 2; ++mi)
#pragma unroll
        for (int h = 0; h < 2; ++h) {
            const int grow = m0 + wm * 32 + mi * 16 + (lane >> 2) + h * 8;
            float* orow = out + (size_t)grow * NDIM;
#pragma unroll
            for (int ni = 0; ni < 4; ++ni) {
                const int col = n0 + wn * 32 + ni * 8 + ((lane & 3) << 1);
                const float b0 = __bfloat162float(__float2bfloat16(bias[col]));
                const float b1 = __bfloat162float(__float2bfloat16(bias[col + 1]));
                const float v0 = __bfloat162float(__float2bfloat16(master[mi][ni][h * 2 + 0]));
                const float v1 = __bfloat162float(__float2bfloat16(master[mi][ni][h * 2 + 1]));
                float2 o;
                o.x = __bfloat162float(__float2bfloat16(v0 + b0));
                o.y = __bfloat162float(__float2bfloat16(v1 + b1));
                *reinterpret_cast<float2*>(orow + col) = o;
            }
        }
}

// ------------------------------ launch ------------------------------
extern "C" void kernel_launch(void* const* d_in, const int* in_sizes, int n_in,
                              void* d_out, int out_size) {
    (void)out_size;
    // Bind inputs BY ELEMENT COUNT:
    //   x: 33554432, w: 16777216, wsi: 1024, bias: 4096
    const float* x    = nullptr;
    const float* w    = nullptr;
    const float* wsi  = nullptr;
    const float* bias = nullptr;
    for (int i = 0; i < n_in; ++i) {
        switch (in_sizes[i]) {
            case 33554432: x    = (const float*)d_in[i]; break;
            case 16777216: w    = (const float*)d_in[i]; break;
            case 1024:     wsi  = (const float*)d_in[i]; break;
            case 4096:     bias = (const float*)d_in[i]; break;
            default: break;
        }
    }
    float* out = (float*)d_out;     // __output__ is float32

    quant_fused_kernel<<<XBLOCKS + WBLOCKS, 256>>>(x, w);

    cudaFuncSetAttribute(gemm_kernel, cudaFuncAttributeMaxDynamicSharedMemorySize, SMEM_TOTAL);
    dim3 grid(NDIM / BN, MDIM / BM);                // (32, 64)
    gemm_kernel<<<grid, THREADS, SMEM_TOTAL>>>(wsi, bias, out);
}